// round 3
// baseline (speedup 1.0000x reference)
#include <cuda_runtime.h>

#define N_NODES 100000
#define N_EDGES 600000
#define F 128
#define CH 32            // K-chunk
#define ST 36            // smem row stride (floats); 36 mod 32 = 4 -> conflict-free LDS128
#define SCAN_B 512
#define NB_SCAN ((N_NODES + SCAN_B - 1) / SCAN_B)   // 196

// ---------------- scratch (device globals: no allocation allowed) -------------
__device__ int   g_deg[N_NODES];
__device__ int   g_cur[N_NODES];
__device__ int   g_off[N_NODES + 1];
__device__ int   g_srcs[N_EDGES];
__device__ int   g_bsum[256];
__device__ float g_agg[(size_t)N_NODES * F];
__device__ float g_h1 [(size_t)N_NODES * F];

// ---------------- CSR build ---------------------------------------------------
__global__ void zero_kernel() {
    int i = blockIdx.x * blockDim.x + threadIdx.x;
    if (i < N_NODES) { g_deg[i] = 0; g_cur[i] = 0; }
}

// edges: int32 [2, E] row-major (JAX demotes int64 -> int32 under default x64=off)
__global__ void hist_kernel(const int* __restrict__ edges) {
    int i = blockIdx.x * blockDim.x + threadIdx.x;
    if (i < N_EDGES) {
        unsigned d = (unsigned)edges[N_EDGES + i];
        if (d < N_NODES) atomicAdd(&g_deg[d], 1);   // guard: wrong dtype -> wrong answer, not crash
    }
}

__global__ void scan1_kernel() {
    __shared__ int s[SCAN_B];
    int i = blockIdx.x * SCAN_B + threadIdx.x;
    int v = (i < N_NODES) ? g_deg[i] : 0;
    s[threadIdx.x] = v;
    __syncthreads();
    for (int off = 1; off < SCAN_B; off <<= 1) {
        int t = (threadIdx.x >= off) ? s[threadIdx.x - off] : 0;
        __syncthreads();
        s[threadIdx.x] += t;
        __syncthreads();
    }
    if (i < N_NODES) g_off[i] = s[threadIdx.x] - v;   // exclusive
    if (threadIdx.x == SCAN_B - 1) g_bsum[blockIdx.x] = s[SCAN_B - 1];
}

__global__ void scan2_kernel() {
    if (threadIdx.x == 0 && blockIdx.x == 0) {
        int acc = 0;
        for (int b = 0; b < NB_SCAN; b++) { int t = g_bsum[b]; g_bsum[b] = acc; acc += t; }
        g_off[N_NODES] = acc;
    }
}

__global__ void scan3_kernel() {
    int i = blockIdx.x * SCAN_B + threadIdx.x;
    if (i < N_NODES) g_off[i] += g_bsum[blockIdx.x];
}

__global__ void fill_kernel(const int* __restrict__ edges) {
    int i = blockIdx.x * blockDim.x + threadIdx.x;
    if (i < N_EDGES) {
        unsigned s = (unsigned)edges[i];
        unsigned d = (unsigned)edges[N_EDGES + i];
        if (s < N_NODES && d < N_NODES) {
            int p = atomicAdd(&g_cur[d], 1);
            g_srcs[g_off[d] + p] = (int)s;
        }
    }
}

// ---------------- mean aggregation: one warp per node -------------------------
// SRC_SEL: 0 -> read from param `in` (x), 1 -> read from g_h1. Output: g_agg.
template <int SRC_SEL>
__global__ void agg_kernel(const float* __restrict__ in) {
    int w = (blockIdx.x * blockDim.x + threadIdx.x) >> 5;
    if (w >= N_NODES) return;
    int lane = threadIdx.x & 31;
    int beg = g_off[w], end = g_off[w + 1];
    const float* src = (SRC_SEL == 0) ? in : (const float*)g_h1;
    const float4* in4 = reinterpret_cast<const float4*>(src);
    float x0 = 0.f, x1 = 0.f, x2 = 0.f, x3 = 0.f;
    for (int e = beg; e < end; e++) {
        int s = g_srcs[e];
        float4 v = in4[(size_t)s * 32 + lane];
        x0 += v.x; x1 += v.y; x2 += v.z; x3 += v.w;
    }
    int d = end - beg;
    float inv = (d > 0) ? (1.0f / (float)d) : 0.0f;
    float4 r; r.x = x0 * inv; r.y = x1 * inv; r.z = x2 * inv; r.w = x3 * inv;
    reinterpret_cast<float4*>(g_agg)[(size_t)w * 32 + lane] = r;
}

// ---------------- fused SAGE GEMM ---------------------------------------------
// Packed f32x2 FMA: accumulator .lo/.hi hold even/odd-K partials.
__device__ __forceinline__ void fma2(float2& d, const float2 a, const float2 b) {
    unsigned long long& rd = reinterpret_cast<unsigned long long&>(d);
    const unsigned long long ra = reinterpret_cast<const unsigned long long&>(a);
    const unsigned long long rb = reinterpret_cast<const unsigned long long&>(b);
    asm("fma.rn.f32x2 %0, %1, %2, %0;" : "+l"(rd) : "l"(ra), "l"(rb));
}

// CFG 1: out(g_h1) = relu(g_agg@W1^T + b + Ap(x)@W2^T)
// CFG 2: out(param) = g_agg@W1^T + b + g_h1@W2^T
// CFG 3: out(param) = Ap@W1^T + b
template <int CFG>
__global__ void __launch_bounds__(256)
gemm_kernel(const float* __restrict__ Ap, const float* __restrict__ W1,
            const float* __restrict__ W2, const float* __restrict__ bias,
            float* __restrict__ outp, int n) {
    __shared__ float sW[F * ST];   // 18,432 B
    __shared__ float sA[F * ST];   // 18,432 B

    const float* A1 = (CFG == 3) ? Ap : (const float*)g_agg;
    const float* A2 = (CFG == 1) ? Ap : (const float*)g_h1;   // unused for CFG 3
    float* out = (CFG == 1) ? (float*)g_h1 : outp;
    const bool RELU = (CFG == 1);
    const int NPASS = (CFG == 3) ? 1 : 2;

    int tid = threadIdx.x;
    int tx = tid & 15, ty = tid >> 4;
    int m0 = blockIdx.x * 128;

    float2 acc[8][8];
#pragma unroll
    for (int mi = 0; mi < 8; mi++)
#pragma unroll
        for (int j = 0; j < 8; j++) acc[mi][j] = make_float2(0.f, 0.f);

    for (int pass = 0; pass < NPASS; pass++) {
        const float* A = (pass == 0) ? A1 : A2;
        const float* W = (pass == 0) ? W1 : W2;
        const float4* A4 = reinterpret_cast<const float4*>(A);
        const float4* W4 = reinterpret_cast<const float4*>(W);

        for (int ck = 0; ck < F / CH; ck++) {
            // load W chunk [128 rows x 32 k] and A chunk
#pragma unroll
            for (int t = tid; t < 128 * (CH / 4); t += 256) {
                int r = t >> 3, c4 = t & 7;
                float4 wv = W4[r * (F / 4) + ck * (CH / 4) + c4];
                *reinterpret_cast<float4*>(&sW[r * ST + 4 * c4]) = wv;
                int m = m0 + r;
                float4 av = (m < n) ? A4[(size_t)m * (F / 4) + ck * (CH / 4) + c4]
                                    : make_float4(0.f, 0.f, 0.f, 0.f);
                *reinterpret_cast<float4*>(&sA[r * ST + 4 * c4]) = av;
            }
            __syncthreads();

#pragma unroll
            for (int k4 = 0; k4 < CH / 4; k4++) {
                float4 w[8];
#pragma unroll
                for (int j = 0; j < 8; j++)
                    w[j] = *reinterpret_cast<const float4*>(&sW[(tx + 16 * j) * ST + 4 * k4]);
#pragma unroll
                for (int mi = 0; mi < 8; mi++) {
                    float4 a = *reinterpret_cast<const float4*>(&sA[(ty * 8 + mi) * ST + 4 * k4]);
                    float2 a01 = make_float2(a.x, a.y);
                    float2 a23 = make_float2(a.z, a.w);
#pragma unroll
                    for (int j = 0; j < 8; j++) {
                        fma2(acc[mi][j], a01, make_float2(w[j].x, w[j].y));
                        fma2(acc[mi][j], a23, make_float2(w[j].z, w[j].w));
                    }
                }
            }
            __syncthreads();
        }
    }

    float bv[8];
#pragma unroll
    for (int j = 0; j < 8; j++) bv[j] = bias[tx + 16 * j];

#pragma unroll
    for (int mi = 0; mi < 8; mi++) {
        int m = m0 + ty * 8 + mi;
        if (m < n) {
#pragma unroll
            for (int j = 0; j < 8; j++) {
                float v = acc[mi][j].x + acc[mi][j].y + bv[j];
                if (RELU) v = fmaxf(v, 0.f);
                out[(size_t)m * F + tx + 16 * j] = v;
            }
        }
    }
}

// ---------------- launch ------------------------------------------------------
extern "C" void kernel_launch(void* const* d_in, const int* in_sizes, int n_in,
                              void* d_out, int out_size) {
    const float* x     = (const float*)d_in[0];
    const int*   xedge = (const int*)d_in[1];      // int32 [2, E]
    const float* w1l   = (const float*)d_in[2];
    const float* b1l   = (const float*)d_in[3];
    const float* w1r   = (const float*)d_in[4];
    const float* w2l   = (const float*)d_in[5];
    const float* b2l   = (const float*)d_in[6];
    const float* w2r   = (const float*)d_in[7];
    const float* wdec  = (const float*)d_in[8];
    const float* bdec  = (const float*)d_in[9];

    float* out_h  = (float*)d_out;
    float* out_dx = out_h + (size_t)N_NODES * F;

    const int gemm_blocks = (N_NODES + 127) / 128;     // 782
    const int agg_blocks  = (N_NODES + 7) / 8;         // 12500 (8 warps/block)

    // CSR build (ints only; rebuilt every call, graph-capturable)
    zero_kernel<<<(N_NODES + 255) / 256, 256>>>();
    hist_kernel<<<(N_EDGES + 255) / 256, 256>>>(xedge);
    scan1_kernel<<<NB_SCAN, SCAN_B>>>();
    scan2_kernel<<<1, 32>>>();
    scan3_kernel<<<NB_SCAN, SCAN_B>>>();
    fill_kernel<<<(N_EDGES + 255) / 256, 256>>>(xedge);

    // Layer 1: agg(x) -> g_agg; g_h1 = relu(g_agg@w1l^T + b1l + x@w1r^T)
    agg_kernel<0><<<agg_blocks, 256>>>(x);
    gemm_kernel<1><<<gemm_blocks, 256>>>(x, w1l, w1r, b1l, nullptr, N_NODES);

    // Layer 2: agg(g_h1) -> g_agg; out_h = g_agg@w2l^T + b2l + g_h1@w2r^T
    agg_kernel<1><<<agg_blocks, 256>>>(nullptr);
    gemm_kernel<2><<<gemm_blocks, 256>>>(nullptr, w2l, w2r, b2l, out_h, N_NODES);

    // Decoder: out_dx = out_h@wdec^T + bdec
    gemm_kernel<3><<<gemm_blocks, 256>>>(out_h, wdec, nullptr, bdec, out_dx, N_NODES);
}

// round 9
// speedup vs baseline: 1.0140x; 1.0140x over previous
#include <cuda_runtime.h>

#define N_NODES 100000
#define N_EDGES 600000
#define F 128
#define CH 32            // K-chunk
#define ST 36            // smem row stride (floats); 36 mod 32 = 4 -> conflict-free LDS128
#define SCAN_B 512
#define NB_SCAN ((N_NODES + SCAN_B - 1) / SCAN_B)   // 196

// ---------------- scratch (device globals: no allocation allowed) -------------
__device__ int   g_deg[N_NODES];
__device__ int   g_cur[N_NODES];
__device__ int   g_off[N_NODES + 1];
__device__ int   g_srcs[N_EDGES];
__device__ int   g_bsum[256];
__device__ float g_agg[(size_t)N_NODES * F];
__device__ float g_h1 [(size_t)N_NODES * F];

// ---------------- CSR build ---------------------------------------------------
__global__ void zero_kernel() {
    int i = blockIdx.x * blockDim.x + threadIdx.x;
    if (i < N_NODES) { g_deg[i] = 0; g_cur[i] = 0; }
}

// edges: int32 [2, E] row-major (JAX default x64=off demotes int64 -> int32)
__global__ void hist_kernel(const int* __restrict__ edges) {
    int i = blockIdx.x * blockDim.x + threadIdx.x;
    if (i < N_EDGES) {
        unsigned d = (unsigned)edges[N_EDGES + i];
        if (d < N_NODES) atomicAdd(&g_deg[d], 1);
    }
}

__global__ void scan1_kernel() {
    __shared__ int s[SCAN_B];
    int i = blockIdx.x * SCAN_B + threadIdx.x;
    int v = (i < N_NODES) ? g_deg[i] : 0;
    s[threadIdx.x] = v;
    __syncthreads();
    for (int off = 1; off < SCAN_B; off <<= 1) {
        int t = (threadIdx.x >= off) ? s[threadIdx.x - off] : 0;
        __syncthreads();
        s[threadIdx.x] += t;
        __syncthreads();
    }
    if (i < N_NODES) g_off[i] = s[threadIdx.x] - v;   // exclusive
    if (threadIdx.x == SCAN_B - 1) g_bsum[blockIdx.x] = s[SCAN_B - 1];
}

__global__ void scan2_kernel() {   // parallel scan over the 196 block sums
    __shared__ int s[256];
    int t = threadIdx.x;
    int v = (t < NB_SCAN) ? g_bsum[t] : 0;
    s[t] = v;
    __syncthreads();
    for (int off = 1; off < 256; off <<= 1) {
        int u = (t >= off) ? s[t - off] : 0;
        __syncthreads();
        s[t] += u;
        __syncthreads();
    }
    if (t < NB_SCAN) g_bsum[t] = s[t] - v;   // exclusive block offsets
    if (t == 255) g_off[N_NODES] = s[255];   // total edge count kept
}

__global__ void scan3_kernel() {
    int i = blockIdx.x * SCAN_B + threadIdx.x;
    if (i < N_NODES) g_off[i] += g_bsum[blockIdx.x];
}

__global__ void fill_kernel(const int* __restrict__ edges) {
    int i = blockIdx.x * blockDim.x + threadIdx.x;
    if (i < N_EDGES) {
        unsigned s = (unsigned)edges[i];
        unsigned d = (unsigned)edges[N_EDGES + i];
        if (s < N_NODES && d < N_NODES) {
            int p = atomicAdd(&g_cur[d], 1);
            g_srcs[g_off[d] + p] = (int)s;
        }
    }
}

// ---------------- mean aggregation: one warp per node, 4-way MLP unroll -------
// SRC_SEL: 0 -> read from param `in` (x), 1 -> read from g_h1. Output: g_agg.
template <int SRC_SEL>
__global__ void agg_kernel(const float* __restrict__ in) {
    int w = (blockIdx.x * blockDim.x + threadIdx.x) >> 5;
    if (w >= N_NODES) return;
    int lane = threadIdx.x & 31;
    int beg = g_off[w], end = g_off[w + 1];
    const float* src = (SRC_SEL == 0) ? in : (const float*)g_h1;
    const float4* in4 = reinterpret_cast<const float4*>(src);
    float x0 = 0.f, x1 = 0.f, x2 = 0.f, x3 = 0.f;
    int e = beg;
    for (; e + 4 <= end; e += 4) {
        int s0 = g_srcs[e], s1 = g_srcs[e + 1], s2 = g_srcs[e + 2], s3 = g_srcs[e + 3];
        float4 v0 = in4[(size_t)s0 * 32 + lane];
        float4 v1 = in4[(size_t)s1 * 32 + lane];
        float4 v2 = in4[(size_t)s2 * 32 + lane];
        float4 v3 = in4[(size_t)s3 * 32 + lane];
        x0 += v0.x + v1.x + v2.x + v3.x;
        x1 += v0.y + v1.y + v2.y + v3.y;
        x2 += v0.z + v1.z + v2.z + v3.z;
        x3 += v0.w + v1.w + v2.w + v3.w;
    }
    for (; e < end; e++) {
        int s = g_srcs[e];
        float4 v = in4[(size_t)s * 32 + lane];
        x0 += v.x; x1 += v.y; x2 += v.z; x3 += v.w;
    }
    int d = end - beg;
    float inv = (d > 0) ? (1.0f / (float)d) : 0.0f;
    float4 r; r.x = x0 * inv; r.y = x1 * inv; r.z = x2 * inv; r.w = x3 * inv;
    reinterpret_cast<float4*>(g_agg)[(size_t)w * 32 + lane] = r;
}

// ---------------- fused SAGE GEMM (proven R3 version, unchanged) --------------
// Packed f32x2 FMA: accumulator .lo/.hi hold even/odd-K partials.
__device__ __forceinline__ void fma2(float2& d, const float2 a, const float2 b) {
    unsigned long long& rd = reinterpret_cast<unsigned long long&>(d);
    const unsigned long long ra = reinterpret_cast<const unsigned long long&>(a);
    const unsigned long long rb = reinterpret_cast<const unsigned long long&>(b);
    asm("fma.rn.f32x2 %0, %1, %2, %0;" : "+l"(rd) : "l"(ra), "l"(rb));
}

// CFG 1: out(g_h1) = relu(g_agg@W1^T + b + Ap(x)@W2^T)
// CFG 2: out(param) = g_agg@W1^T + b + g_h1@W2^T
// CFG 3: out(param) = Ap@W1^T + b
template <int CFG>
__global__ void __launch_bounds__(256)
gemm_kernel(const float* __restrict__ Ap, const float* __restrict__ W1,
            const float* __restrict__ W2, const float* __restrict__ bias,
            float* __restrict__ outp, int n) {
    __shared__ float sW[F * ST];   // 18,432 B
    __shared__ float sA[F * ST];   // 18,432 B

    const float* A1 = (CFG == 3) ? Ap : (const float*)g_agg;
    const float* A2 = (CFG == 1) ? Ap : (const float*)g_h1;   // unused for CFG 3
    float* out = (CFG == 1) ? (float*)g_h1 : outp;
    const bool RELU = (CFG == 1);
    const int NPASS = (CFG == 3) ? 1 : 2;

    int tid = threadIdx.x;
    int tx = tid & 15, ty = tid >> 4;
    int m0 = blockIdx.x * 128;

    float2 acc[8][8];
#pragma unroll
    for (int mi = 0; mi < 8; mi++)
#pragma unroll
        for (int j = 0; j < 8; j++) acc[mi][j] = make_float2(0.f, 0.f);

    for (int pass = 0; pass < NPASS; pass++) {
        const float* A = (pass == 0) ? A1 : A2;
        const float* W = (pass == 0) ? W1 : W2;
        const float4* A4 = reinterpret_cast<const float4*>(A);
        const float4* W4 = reinterpret_cast<const float4*>(W);

        for (int ck = 0; ck < F / CH; ck++) {
            // load W chunk [128 rows x 32 k] and A chunk
#pragma unroll
            for (int t = tid; t < 128 * (CH / 4); t += 256) {
                int r = t >> 3, c4 = t & 7;
                float4 wv = W4[r * (F / 4) + ck * (CH / 4) + c4];
                *reinterpret_cast<float4*>(&sW[r * ST + 4 * c4]) = wv;
                int m = m0 + r;
                float4 av = (m < n) ? A4[(size_t)m * (F / 4) + ck * (CH / 4) + c4]
                                    : make_float4(0.f, 0.f, 0.f, 0.f);
                *reinterpret_cast<float4*>(&sA[r * ST + 4 * c4]) = av;
            }
            __syncthreads();

#pragma unroll
            for (int k4 = 0; k4 < CH / 4; k4++) {
                float4 w[8];
#pragma unroll
                for (int j = 0; j < 8; j++)
                    w[j] = *reinterpret_cast<const float4*>(&sW[(tx + 16 * j) * ST + 4 * k4]);
#pragma unroll
                for (int mi = 0; mi < 8; mi++) {
                    float4 a = *reinterpret_cast<const float4*>(&sA[(ty * 8 + mi) * ST + 4 * k4]);
                    float2 a01 = make_float2(a.x, a.y);
                    float2 a23 = make_float2(a.z, a.w);
#pragma unroll
                    for (int j = 0; j < 8; j++) {
                        fma2(acc[mi][j], a01, make_float2(w[j].x, w[j].y));
                        fma2(acc[mi][j], a23, make_float2(w[j].z, w[j].w));
                    }
                }
            }
            __syncthreads();
        }
    }

    float bv[8];
#pragma unroll
    for (int j = 0; j < 8; j++) bv[j] = bias[tx + 16 * j];

#pragma unroll
    for (int mi = 0; mi < 8; mi++) {
        int m = m0 + ty * 8 + mi;
        if (m < n) {
#pragma unroll
            for (int j = 0; j < 8; j++) {
                float v = acc[mi][j].x + acc[mi][j].y + bv[j];
                if (RELU) v = fmaxf(v, 0.f);
                out[(size_t)m * F + tx + 16 * j] = v;
            }
        }
    }
}

// ---------------- launch ------------------------------------------------------
extern "C" void kernel_launch(void* const* d_in, const int* in_sizes, int n_in,
                              void* d_out, int out_size) {
    const float* x     = (const float*)d_in[0];
    const int*   xedge = (const int*)d_in[1];      // int32 [2, E]
    const float* w1l   = (const float*)d_in[2];
    const float* b1l   = (const float*)d_in[3];
    const float* w1r   = (const float*)d_in[4];
    const float* w2l   = (const float*)d_in[5];
    const float* b2l   = (const float*)d_in[6];
    const float* w2r   = (const float*)d_in[7];
    const float* wdec  = (const float*)d_in[8];
    const float* bdec  = (const float*)d_in[9];

    float* out_h  = (float*)d_out;
    float* out_dx = out_h + (size_t)N_NODES * F;

    const int gemm_blocks = (N_NODES + 127) / 128;     // 782
    const int agg_blocks  = (N_NODES + 7) / 8;         // 12500 (8 warps/block)

    // CSR build (ints only; rebuilt every call, graph-capturable)
    zero_kernel<<<(N_NODES + 255) / 256, 256>>>();
    hist_kernel<<<(N_EDGES + 255) / 256, 256>>>(xedge);
    scan1_kernel<<<NB_SCAN, SCAN_B>>>();
    scan2_kernel<<<1, 256>>>();
    scan3_kernel<<<NB_SCAN, SCAN_B>>>();
    fill_kernel<<<(N_EDGES + 255) / 256, 256>>>(xedge);

    // Layer 1: agg(x) -> g_agg; g_h1 = relu(g_agg@w1l^T + b1l + x@w1r^T)
    agg_kernel<0><<<agg_blocks, 256>>>(x);
    gemm_kernel<1><<<gemm_blocks, 256>>>(x, w1l, w1r, b1l, nullptr, N_NODES);

    // Layer 2: agg(g_h1) -> g_agg; out_h = g_agg@w2l^T + b2l + g_h1@w2r^T
    agg_kernel<1><<<agg_blocks, 256>>>(nullptr);
    gemm_kernel<2><<<gemm_blocks, 256>>>(nullptr, w2l, w2r, b2l, out_h, N_NODES);

    // Decoder: out_dx = out_h@wdec^T + bdec
    gemm_kernel<3><<<gemm_blocks, 256>>>(out_h, wdec, nullptr, bdec, out_dx, N_NODES);
}

// round 10
// speedup vs baseline: 1.0953x; 1.0802x over previous
#include <cuda_runtime.h>
#include <cuda_bf16.h>

#define N_NODES 100000
#define N_EDGES 600000
#define F 128
#define CH 32            // K-chunk (fp32 gemm)
#define ST 36            // smem row stride (floats); conflict-free LDS128
#define SCAN_B 512
#define NB_SCAN ((N_NODES + SCAN_B - 1) / SCAN_B)   // 196

// ---------------- scratch (device globals: proven-safe set) -------------------
__device__ int   g_deg[N_NODES];
__device__ int   g_cur[N_NODES];
__device__ int   g_off[N_NODES + 1];
__device__ int   g_srcs[N_EDGES];
__device__ int   g_bsum[256];
__device__ float g_agg[(size_t)N_NODES * F];
__device__ float g_h1 [(size_t)N_NODES * F];

// ---------------- CSR build ---------------------------------------------------
__global__ void zero_kernel() {
    int i = blockIdx.x * blockDim.x + threadIdx.x;
    if (i < N_NODES) { g_deg[i] = 0; g_cur[i] = 0; }
}

__global__ void hist_kernel(const int* __restrict__ edges) {
    int i = blockIdx.x * blockDim.x + threadIdx.x;
    if (i < N_EDGES) {
        unsigned d = (unsigned)edges[N_EDGES + i];
        if (d < N_NODES) atomicAdd(&g_deg[d], 1);
    }
}

__global__ void scan1_kernel() {
    __shared__ int s[SCAN_B];
    int i = blockIdx.x * SCAN_B + threadIdx.x;
    int v = (i < N_NODES) ? g_deg[i] : 0;
    s[threadIdx.x] = v;
    __syncthreads();
    for (int off = 1; off < SCAN_B; off <<= 1) {
        int t = (threadIdx.x >= off) ? s[threadIdx.x - off] : 0;
        __syncthreads();
        s[threadIdx.x] += t;
        __syncthreads();
    }
    if (i < N_NODES) g_off[i] = s[threadIdx.x] - v;
    if (threadIdx.x == SCAN_B - 1) g_bsum[blockIdx.x] = s[SCAN_B - 1];
}

__global__ void scan2_kernel() {
    __shared__ int s[256];
    int t = threadIdx.x;
    int v = (t < NB_SCAN) ? g_bsum[t] : 0;
    s[t] = v;
    __syncthreads();
    for (int off = 1; off < 256; off <<= 1) {
        int u = (t >= off) ? s[t - off] : 0;
        __syncthreads();
        s[t] += u;
        __syncthreads();
    }
    if (t < NB_SCAN) g_bsum[t] = s[t] - v;
    if (t == 255) g_off[N_NODES] = s[255];
}

__global__ void scan3_kernel() {
    int i = blockIdx.x * SCAN_B + threadIdx.x;
    if (i < N_NODES) g_off[i] += g_bsum[blockIdx.x];
}

__global__ void fill_kernel(const int* __restrict__ edges) {
    int i = blockIdx.x * blockDim.x + threadIdx.x;
    if (i < N_EDGES) {
        unsigned s = (unsigned)edges[i];
        unsigned d = (unsigned)edges[N_EDGES + i];
        if (s < N_NODES && d < N_NODES) {
            int p = atomicAdd(&g_cur[d], 1);
            g_srcs[g_off[d] + p] = (int)s;
        }
    }
}

// ---------------- mean aggregation: one warp per node, 4-way MLP unroll -------
template <int SRC_SEL>
__global__ void agg_kernel(const float* __restrict__ in) {
    int w = (blockIdx.x * blockDim.x + threadIdx.x) >> 5;
    if (w >= N_NODES) return;
    int lane = threadIdx.x & 31;
    int beg = g_off[w], end = g_off[w + 1];
    const float* src = (SRC_SEL == 0) ? in : (const float*)g_h1;
    const float4* in4 = reinterpret_cast<const float4*>(src);
    float x0 = 0.f, x1 = 0.f, x2 = 0.f, x3 = 0.f;
    int e = beg;
    for (; e + 4 <= end; e += 4) {
        int s0 = g_srcs[e], s1 = g_srcs[e + 1], s2 = g_srcs[e + 2], s3 = g_srcs[e + 3];
        float4 v0 = in4[(size_t)s0 * 32 + lane];
        float4 v1 = in4[(size_t)s1 * 32 + lane];
        float4 v2 = in4[(size_t)s2 * 32 + lane];
        float4 v3 = in4[(size_t)s3 * 32 + lane];
        x0 += v0.x + v1.x + v2.x + v3.x;
        x1 += v0.y + v1.y + v2.y + v3.y;
        x2 += v0.z + v1.z + v2.z + v3.z;
        x3 += v0.w + v1.w + v2.w + v3.w;
    }
    for (; e < end; e++) {
        int s = g_srcs[e];
        float4 v = in4[(size_t)s * 32 + lane];
        x0 += v.x; x1 += v.y; x2 += v.z; x3 += v.w;
    }
    int d = end - beg;
    float inv = (d > 0) ? (1.0f / (float)d) : 0.0f;
    float4 r; r.x = x0 * inv; r.y = x1 * inv; r.z = x2 * inv; r.w = x3 * inv;
    reinterpret_cast<float4*>(g_agg)[(size_t)w * 32 + lane] = r;
}

// ---------------- fused SAGE GEMM (proven fp32 version; layers 1+2) -----------
__device__ __forceinline__ void fma2(float2& d, const float2 a, const float2 b) {
    unsigned long long& rd = reinterpret_cast<unsigned long long&>(d);
    const unsigned long long ra = reinterpret_cast<const unsigned long long&>(a);
    const unsigned long long rb = reinterpret_cast<const unsigned long long&>(b);
    asm("fma.rn.f32x2 %0, %1, %2, %0;" : "+l"(rd) : "l"(ra), "l"(rb));
}

// CFG 1: out(g_h1) = relu(g_agg@W1^T + b + Ap(x)@W2^T)
// CFG 2: out(param) = g_agg@W1^T + b + g_h1@W2^T
template <int CFG>
__global__ void __launch_bounds__(256)
gemm_kernel(const float* __restrict__ Ap, const float* __restrict__ W1,
            const float* __restrict__ W2, const float* __restrict__ bias,
            float* __restrict__ outp, int n) {
    __shared__ float sW[F * ST];
    __shared__ float sA[F * ST];

    const float* A1 = (const float*)g_agg;
    const float* A2 = (CFG == 1) ? Ap : (const float*)g_h1;
    float* out = (CFG == 1) ? (float*)g_h1 : outp;
    const bool RELU = (CFG == 1);

    int tid = threadIdx.x;
    int tx = tid & 15, ty = tid >> 4;
    int m0 = blockIdx.x * 128;

    float2 acc[8][8];
#pragma unroll
    for (int mi = 0; mi < 8; mi++)
#pragma unroll
        for (int j = 0; j < 8; j++) acc[mi][j] = make_float2(0.f, 0.f);

    for (int pass = 0; pass < 2; pass++) {
        const float* A = (pass == 0) ? A1 : A2;
        const float* W = (pass == 0) ? W1 : W2;
        const float4* A4 = reinterpret_cast<const float4*>(A);
        const float4* W4 = reinterpret_cast<const float4*>(W);

        for (int ck = 0; ck < F / CH; ck++) {
#pragma unroll
            for (int t = tid; t < 128 * (CH / 4); t += 256) {
                int r = t >> 3, c4 = t & 7;
                float4 wv = W4[r * (F / 4) + ck * (CH / 4) + c4];
                *reinterpret_cast<float4*>(&sW[r * ST + 4 * c4]) = wv;
                int m = m0 + r;
                float4 av = (m < n) ? A4[(size_t)m * (F / 4) + ck * (CH / 4) + c4]
                                    : make_float4(0.f, 0.f, 0.f, 0.f);
                *reinterpret_cast<float4*>(&sA[r * ST + 4 * c4]) = av;
            }
            __syncthreads();

#pragma unroll
            for (int k4 = 0; k4 < CH / 4; k4++) {
                float4 w[8];
#pragma unroll
                for (int j = 0; j < 8; j++)
                    w[j] = *reinterpret_cast<const float4*>(&sW[(tx + 16 * j) * ST + 4 * k4]);
#pragma unroll
                for (int mi = 0; mi < 8; mi++) {
                    float4 a = *reinterpret_cast<const float4*>(&sA[(ty * 8 + mi) * ST + 4 * k4]);
                    float2 a01 = make_float2(a.x, a.y);
                    float2 a23 = make_float2(a.z, a.w);
#pragma unroll
                    for (int j = 0; j < 8; j++) {
                        fma2(acc[mi][j], a01, make_float2(w[j].x, w[j].y));
                        fma2(acc[mi][j], a23, make_float2(w[j].z, w[j].w));
                    }
                }
            }
            __syncthreads();
        }
    }

    float bv[8];
#pragma unroll
    for (int j = 0; j < 8; j++) bv[j] = bias[tx + 16 * j];

#pragma unroll
    for (int mi = 0; mi < 8; mi++) {
        int m = m0 + ty * 8 + mi;
        if (m < n) {
#pragma unroll
            for (int j = 0; j < 8; j++) {
                float v = acc[mi][j].x + acc[mi][j].y + bv[j];
                if (RELU) v = fmaxf(v, 0.f);
                out[(size_t)m * F + tx + 16 * j] = v;
            }
        }
    }
}

// ---------------- decoder: mma.sync bf16 split probe --------------------------
// out[64m x 128n per block] = h@wdec^T + b. 8 warps, warp tile 32x32.
// smem: Ah[0,5120) Al[5120,10240) Wh[10240,20480) Wl[20480,30720); row stride 80B.
#define MMAS(c0, c1, c2, c3, a0, a1, a2, a3, b0, b1) \
    asm volatile("mma.sync.aligned.m16n8k16.row.col.f32.bf16.bf16.f32 " \
        "{%0,%1,%2,%3}, {%4,%5,%6,%7}, {%8,%9}, {%0,%1,%2,%3};" \
        : "+f"(c0), "+f"(c1), "+f"(c2), "+f"(c3) \
        : "r"(a0), "r"(a1), "r"(a2), "r"(a3), "r"(b0), "r"(b1))

#define DACC(mt, nt) \
    float C##mt##nt##_0 = 0.f, C##mt##nt##_1 = 0.f, C##mt##nt##_2 = 0.f, C##mt##nt##_3 = 0.f

#define LDA(mt) \
    unsigned AH##mt##_0, AH##mt##_1, AH##mt##_2, AH##mt##_3; \
    unsigned AL##mt##_0, AL##mt##_1, AL##mt##_2, AL##mt##_3; \
    { unsigned o_ = aBase + (unsigned)(mt * 16 * 80) + kb; \
      AH##mt##_0 = *reinterpret_cast<const unsigned*>(sm + o_); \
      AH##mt##_1 = *reinterpret_cast<const unsigned*>(sm + o_ + 640); \
      AH##mt##_2 = *reinterpret_cast<const unsigned*>(sm + o_ + 16); \
      AH##mt##_3 = *reinterpret_cast<const unsigned*>(sm + o_ + 656); \
      AL##mt##_0 = *reinterpret_cast<const unsigned*>(sm + o_ + 5120); \
      AL##mt##_1 = *reinterpret_cast<const unsigned*>(sm + o_ + 5760); \
      AL##mt##_2 = *reinterpret_cast<const unsigned*>(sm + o_ + 5136); \
      AL##mt##_3 = *reinterpret_cast<const unsigned*>(sm + o_ + 5776); }

#define LDW(nt) \
    unsigned WH##nt##_0, WH##nt##_1, WL##nt##_0, WL##nt##_1; \
    { unsigned o_ = wBase + (unsigned)(nt * 8 * 80) + kb; \
      WH##nt##_0 = *reinterpret_cast<const unsigned*>(sm + o_); \
      WH##nt##_1 = *reinterpret_cast<const unsigned*>(sm + o_ + 16); \
      WL##nt##_0 = *reinterpret_cast<const unsigned*>(sm + o_ + 10240); \
      WL##nt##_1 = *reinterpret_cast<const unsigned*>(sm + o_ + 10256); }

#define DOMMA(mt, nt) \
    MMAS(C##mt##nt##_0, C##mt##nt##_1, C##mt##nt##_2, C##mt##nt##_3, \
         AH##mt##_0, AH##mt##_1, AH##mt##_2, AH##mt##_3, WH##nt##_0, WH##nt##_1); \
    MMAS(C##mt##nt##_0, C##mt##nt##_1, C##mt##nt##_2, C##mt##nt##_3, \
         AH##mt##_0, AH##mt##_1, AH##mt##_2, AH##mt##_3, WL##nt##_0, WL##nt##_1); \
    MMAS(C##mt##nt##_0, C##mt##nt##_1, C##mt##nt##_2, C##mt##nt##_3, \
         AL##mt##_0, AL##mt##_1, AL##mt##_2, AL##mt##_3, WH##nt##_0, WH##nt##_1)

#define DEC_KS(kb_) { \
    unsigned kb = (kb_); \
    LDA(0) LDA(1) LDW(0) LDW(1) LDW(2) LDW(3) \
    DOMMA(0, 0); DOMMA(0, 1); DOMMA(0, 2); DOMMA(0, 3); \
    DOMMA(1, 0); DOMMA(1, 1); DOMMA(1, 2); DOMMA(1, 3); }

#define DEPI(mt, nt) { \
    int nc = wn * 32 + nt * 8 + 2 * r4; \
    int m = m0 + wm * 32 + mt * 16 + q4; \
    float v0 = C##mt##nt##_0 + bias[nc], v1 = C##mt##nt##_1 + bias[nc + 1]; \
    float v2 = C##mt##nt##_2 + bias[nc], v3 = C##mt##nt##_3 + bias[nc + 1]; \
    if (m < n) *reinterpret_cast<float2*>(&out[(size_t)m * F + nc]) = make_float2(v0, v1); \
    if (m + 8 < n) *reinterpret_cast<float2*>(&out[(size_t)(m + 8) * F + nc]) = make_float2(v2, v3); }

// split v -> bf16 hi/lo packed pair helper (fully inline, scalar)
#define SPLITPACK(vx, vy, hp_, lp_) { \
    __nv_bfloat16 h0_ = __float2bfloat16_rn(vx); \
    __nv_bfloat16 h1_ = __float2bfloat16_rn(vy); \
    __nv_bfloat16 l0_ = __float2bfloat16_rn((vx) - __bfloat162float(h0_)); \
    __nv_bfloat16 l1_ = __float2bfloat16_rn((vy) - __bfloat162float(h1_)); \
    hp_ = (unsigned)__bfloat16_as_ushort(h0_) | ((unsigned)__bfloat16_as_ushort(h1_) << 16); \
    lp_ = (unsigned)__bfloat16_as_ushort(l0_) | ((unsigned)__bfloat16_as_ushort(l1_) << 16); }

__global__ void __launch_bounds__(256)
dec_mma(const float* __restrict__ h, const float* __restrict__ w,
        const float* __restrict__ bias, float* __restrict__ out, int n) {
    __shared__ __align__(16) char sm[30720];

    int tid = threadIdx.x, lane = tid & 31, wid = tid >> 5;
    int wm = wid & 1, wn = wid >> 1;           // 2 m-warps x 4 n-warps
    int q4 = lane >> 2, r4 = lane & 3;
    int m0 = blockIdx.x * 64;

    DACC(0, 0); DACC(0, 1); DACC(0, 2); DACC(0, 3);
    DACC(1, 0); DACC(1, 1); DACC(1, 2); DACC(1, 3);

    unsigned aBase = (unsigned)((wm * 32 + q4) * 80 + r4 * 4);
    unsigned wBase = (unsigned)(10240 + (wn * 32 + q4) * 80 + r4 * 4);

    const float4* h4 = reinterpret_cast<const float4*>(h);
    const float4* w4 = reinterpret_cast<const float4*>(w);

    for (int ck = 0; ck < 4; ck++) {
        __syncthreads();
        // A: 64 rows x 32 k fp32 -> split planes. 2 float4/thread.
#pragma unroll
        for (int i = 0; i < 2; i++) {
            int f = tid * 2 + i;                 // 0..511
            int row = f >> 3, j = f & 7;
            float4 v = make_float4(0.f, 0.f, 0.f, 0.f);
            if (m0 + row < n) v = h4[(size_t)(m0 + row) * 32 + ck * 8 + j];
            unsigned hp0, lp0, hp1, lp1;
            SPLITPACK(v.x, v.y, hp0, lp0);
            SPLITPACK(v.z, v.w, hp1, lp1);
            *reinterpret_cast<uint2*>(sm + row * 80 + j * 8) = make_uint2(hp0, hp1);
            *reinterpret_cast<uint2*>(sm + 5120 + row * 80 + j * 8) = make_uint2(lp0, lp1);
        }
        // W: 128 rows x 32 k fp32 -> split planes. 4 float4/thread.
#pragma unroll
        for (int i = 0; i < 4; i++) {
            int f = tid + i * 256;               // 0..1023
            int row = f >> 3, j = f & 7;
            float4 v = w4[(size_t)row * 32 + ck * 8 + j];
            unsigned hp0, lp0, hp1, lp1;
            SPLITPACK(v.x, v.y, hp0, lp0);
            SPLITPACK(v.z, v.w, hp1, lp1);
            *reinterpret_cast<uint2*>(sm + 10240 + row * 80 + j * 8) = make_uint2(hp0, hp1);
            *reinterpret_cast<uint2*>(sm + 20480 + row * 80 + j * 8) = make_uint2(lp0, lp1);
        }
        __syncthreads();
        DEC_KS(0u)
        DEC_KS(32u)
    }

    DEPI(0, 0) DEPI(0, 1) DEPI(0, 2) DEPI(0, 3)
    DEPI(1, 0) DEPI(1, 1) DEPI(1, 2) DEPI(1, 3)
}

// ---------------- launch ------------------------------------------------------
extern "C" void kernel_launch(void* const* d_in, const int* in_sizes, int n_in,
                              void* d_out, int out_size) {
    const float* x     = (const float*)d_in[0];
    const int*   xedge = (const int*)d_in[1];      // int32 [2, E]
    const float* w1l   = (const float*)d_in[2];
    const float* b1l   = (const float*)d_in[3];
    const float* w1r   = (const float*)d_in[4];
    const float* w2l   = (const float*)d_in[5];
    const float* b2l   = (const float*)d_in[6];
    const float* w2r   = (const float*)d_in[7];
    const float* wdec  = (const float*)d_in[8];
    const float* bdec  = (const float*)d_in[9];

    float* out_h  = (float*)d_out;
    float* out_dx = out_h + (size_t)N_NODES * F;

    const int gemm_blocks = (N_NODES + 127) / 128;     // 782
    const int agg_blocks  = (N_NODES + 7) / 8;         // 12500
    const int dec_blocks  = (N_NODES + 63) / 64;       // 1563

    // CSR build
    zero_kernel<<<(N_NODES + 255) / 256, 256>>>();
    hist_kernel<<<(N_EDGES + 255) / 256, 256>>>(xedge);
    scan1_kernel<<<NB_SCAN, SCAN_B>>>();
    scan2_kernel<<<1, 256>>>();
    scan3_kernel<<<NB_SCAN, SCAN_B>>>();
    fill_kernel<<<(N_EDGES + 255) / 256, 256>>>(xedge);

    // Layer 1: agg(x) -> g_agg; g_h1 = relu(g_agg@w1l^T + b1l + x@w1r^T)
    agg_kernel<0><<<agg_blocks, 256>>>(x);
    gemm_kernel<1><<<gemm_blocks, 256>>>(x, w1l, w1r, b1l, nullptr, N_NODES);

    // Layer 2: agg(g_h1) -> g_agg; out_h = g_agg@w2l^T + b2l + g_h1@w2r^T
    agg_kernel<1><<<agg_blocks, 256>>>(nullptr);
    gemm_kernel<2><<<gemm_blocks, 256>>>(nullptr, w2l, w2r, b2l, out_h, N_NODES);

    // Decoder (tensor-core probe): out_dx = out_h@wdec^T + bdec
    dec_mma<<<dec_blocks, 256>>>(out_h, wdec, bdec, out_dx, N_NODES);
}

// round 11
// speedup vs baseline: 1.6887x; 1.5417x over previous
#include <cuda_runtime.h>
#include <cuda_bf16.h>

#define N_NODES 100000
#define N_EDGES 600000
#define F 128
#define SCAN_B 512
#define NB_SCAN ((N_NODES + SCAN_B - 1) / SCAN_B)   // 196

// ---------------- scratch (device globals: proven-safe set) -------------------
__device__ int   g_deg[N_NODES];
__device__ int   g_cur[N_NODES];
__device__ int   g_off[N_NODES + 1];
__device__ int   g_srcs[N_EDGES];
__device__ int   g_bsum[256];
__device__ float g_agg[(size_t)N_NODES * F];
__device__ float g_h1 [(size_t)N_NODES * F];

// ---------------- CSR build ---------------------------------------------------
__global__ void zero_kernel() {
    int i = blockIdx.x * blockDim.x + threadIdx.x;
    if (i < N_NODES) { g_deg[i] = 0; g_cur[i] = 0; }
}

__global__ void hist_kernel(const int* __restrict__ edges) {
    int i = blockIdx.x * blockDim.x + threadIdx.x;
    if (i < N_EDGES) {
        unsigned d = (unsigned)edges[N_EDGES + i];
        if (d < N_NODES) atomicAdd(&g_deg[d], 1);
    }
}

__global__ void scan1_kernel() {
    __shared__ int s[SCAN_B];
    int i = blockIdx.x * SCAN_B + threadIdx.x;
    int v = (i < N_NODES) ? g_deg[i] : 0;
    s[threadIdx.x] = v;
    __syncthreads();
    for (int off = 1; off < SCAN_B; off <<= 1) {
        int t = (threadIdx.x >= off) ? s[threadIdx.x - off] : 0;
        __syncthreads();
        s[threadIdx.x] += t;
        __syncthreads();
    }
    if (i < N_NODES) g_off[i] = s[threadIdx.x] - v;
    if (threadIdx.x == SCAN_B - 1) g_bsum[blockIdx.x] = s[SCAN_B - 1];
}

__global__ void scan2_kernel() {
    __shared__ int s[256];
    int t = threadIdx.x;
    int v = (t < NB_SCAN) ? g_bsum[t] : 0;
    s[t] = v;
    __syncthreads();
    for (int off = 1; off < 256; off <<= 1) {
        int u = (t >= off) ? s[t - off] : 0;
        __syncthreads();
        s[t] += u;
        __syncthreads();
    }
    if (t < NB_SCAN) g_bsum[t] = s[t] - v;
    if (t == 255) g_off[N_NODES] = s[255];
}

__global__ void scan3_kernel() {
    int i = blockIdx.x * SCAN_B + threadIdx.x;
    if (i < N_NODES) g_off[i] += g_bsum[blockIdx.x];
}

__global__ void fill_kernel(const int* __restrict__ edges) {
    int i = blockIdx.x * blockDim.x + threadIdx.x;
    if (i < N_EDGES) {
        unsigned s = (unsigned)edges[i];
        unsigned d = (unsigned)edges[N_EDGES + i];
        if (s < N_NODES && d < N_NODES) {
            int p = atomicAdd(&g_cur[d], 1);
            g_srcs[g_off[d] + p] = (int)s;
        }
    }
}

// ---------------- mean aggregation: one warp per node, 4-way MLP unroll -------
template <int SRC_SEL>
__global__ void agg_kernel(const float* __restrict__ in) {
    int w = (blockIdx.x * blockDim.x + threadIdx.x) >> 5;
    if (w >= N_NODES) return;
    int lane = threadIdx.x & 31;
    int beg = g_off[w], end = g_off[w + 1];
    const float* src = (SRC_SEL == 0) ? in : (const float*)g_h1;
    const float4* in4 = reinterpret_cast<const float4*>(src);
    float x0 = 0.f, x1 = 0.f, x2 = 0.f, x3 = 0.f;
    int e = beg;
    for (; e + 4 <= end; e += 4) {
        int s0 = g_srcs[e], s1 = g_srcs[e + 1], s2 = g_srcs[e + 2], s3 = g_srcs[e + 3];
        float4 v0 = in4[(size_t)s0 * 32 + lane];
        float4 v1 = in4[(size_t)s1 * 32 + lane];
        float4 v2 = in4[(size_t)s2 * 32 + lane];
        float4 v3 = in4[(size_t)s3 * 32 + lane];
        x0 += v0.x + v1.x + v2.x + v3.x;
        x1 += v0.y + v1.y + v2.y + v3.y;
        x2 += v0.z + v1.z + v2.z + v3.z;
        x3 += v0.w + v1.w + v2.w + v3.w;
    }
    for (; e < end; e++) {
        int s = g_srcs[e];
        float4 v = in4[(size_t)s * 32 + lane];
        x0 += v.x; x1 += v.y; x2 += v.z; x3 += v.w;
    }
    int d = end - beg;
    float inv = (d > 0) ? (1.0f / (float)d) : 0.0f;
    float4 r; r.x = x0 * inv; r.y = x1 * inv; r.z = x2 * inv; r.w = x3 * inv;
    reinterpret_cast<float4*>(g_agg)[(size_t)w * 32 + lane] = r;
}

// ---------------- mma.sync bf16-split GEMM (proven R10 decoder style) ---------
// Per block: out[64m x 128n] = sum_pass A_pass@W_pass^T (+bias, opt relu).
// smem: Ah[0,5120) Al[5120,10240) Wh[10240,20480) Wl[20480,30720); row stride 80B.
#define MMAS(c0, c1, c2, c3, a0, a1, a2, a3, b0, b1) \
    asm volatile("mma.sync.aligned.m16n8k16.row.col.f32.bf16.bf16.f32 " \
        "{%0,%1,%2,%3}, {%4,%5,%6,%7}, {%8,%9}, {%0,%1,%2,%3};" \
        : "+f"(c0), "+f"(c1), "+f"(c2), "+f"(c3) \
        : "r"(a0), "r"(a1), "r"(a2), "r"(a3), "r"(b0), "r"(b1))

#define DACC(mt, nt) \
    float C##mt##nt##_0 = 0.f, C##mt##nt##_1 = 0.f, C##mt##nt##_2 = 0.f, C##mt##nt##_3 = 0.f

#define LDA(mt) \
    unsigned AH##mt##_0, AH##mt##_1, AH##mt##_2, AH##mt##_3; \
    unsigned AL##mt##_0, AL##mt##_1, AL##mt##_2, AL##mt##_3; \
    { unsigned o_ = aBase + (unsigned)(mt * 16 * 80) + kb; \
      AH##mt##_0 = *reinterpret_cast<const unsigned*>(sm + o_); \
      AH##mt##_1 = *reinterpret_cast<const unsigned*>(sm + o_ + 640); \
      AH##mt##_2 = *reinterpret_cast<const unsigned*>(sm + o_ + 16); \
      AH##mt##_3 = *reinterpret_cast<const unsigned*>(sm + o_ + 656); \
      AL##mt##_0 = *reinterpret_cast<const unsigned*>(sm + o_ + 5120); \
      AL##mt##_1 = *reinterpret_cast<const unsigned*>(sm + o_ + 5760); \
      AL##mt##_2 = *reinterpret_cast<const unsigned*>(sm + o_ + 5136); \
      AL##mt##_3 = *reinterpret_cast<const unsigned*>(sm + o_ + 5776); }

#define LDW(nt) \
    unsigned WH##nt##_0, WH##nt##_1, WL##nt##_0, WL##nt##_1; \
    { unsigned o_ = wBase + (unsigned)(nt * 8 * 80) + kb; \
      WH##nt##_0 = *reinterpret_cast<const unsigned*>(sm + o_); \
      WH##nt##_1 = *reinterpret_cast<const unsigned*>(sm + o_ + 16); \
      WL##nt##_0 = *reinterpret_cast<const unsigned*>(sm + o_ + 10240); \
      WL##nt##_1 = *reinterpret_cast<const unsigned*>(sm + o_ + 10256); }

#define DOMMA(mt, nt) \
    MMAS(C##mt##nt##_0, C##mt##nt##_1, C##mt##nt##_2, C##mt##nt##_3, \
         AH##mt##_0, AH##mt##_1, AH##mt##_2, AH##mt##_3, WH##nt##_0, WH##nt##_1); \
    MMAS(C##mt##nt##_0, C##mt##nt##_1, C##mt##nt##_2, C##mt##nt##_3, \
         AH##mt##_0, AH##mt##_1, AH##mt##_2, AH##mt##_3, WL##nt##_0, WL##nt##_1); \
    MMAS(C##mt##nt##_0, C##mt##nt##_1, C##mt##nt##_2, C##mt##nt##_3, \
         AL##mt##_0, AL##mt##_1, AL##mt##_2, AL##mt##_3, WH##nt##_0, WH##nt##_1)

#define DEC_KS(kb_) { \
    unsigned kb = (kb_); \
    LDA(0) LDA(1) LDW(0) LDW(1) LDW(2) LDW(3) \
    DOMMA(0, 0); DOMMA(0, 1); DOMMA(0, 2); DOMMA(0, 3); \
    DOMMA(1, 0); DOMMA(1, 1); DOMMA(1, 2); DOMMA(1, 3); }

#define DEPI(mt, nt) { \
    int nc = wn * 32 + nt * 8 + 2 * r4; \
    int m = m0 + wm * 32 + mt * 16 + q4; \
    float v0 = C##mt##nt##_0 + bias[nc], v1 = C##mt##nt##_1 + bias[nc + 1]; \
    float v2 = C##mt##nt##_2 + bias[nc], v3 = C##mt##nt##_3 + bias[nc + 1]; \
    if (RELU) { v0 = fmaxf(v0, 0.f); v1 = fmaxf(v1, 0.f); \
                v2 = fmaxf(v2, 0.f); v3 = fmaxf(v3, 0.f); } \
    if (m < n) *reinterpret_cast<float2*>(&out[(size_t)m * F + nc]) = make_float2(v0, v1); \
    if (m + 8 < n) *reinterpret_cast<float2*>(&out[(size_t)(m + 8) * F + nc]) = make_float2(v2, v3); }

#define SPLITPACK(vx, vy, hp_, lp_) { \
    __nv_bfloat16 h0_ = __float2bfloat16_rn(vx); \
    __nv_bfloat16 h1_ = __float2bfloat16_rn(vy); \
    __nv_bfloat16 l0_ = __float2bfloat16_rn((vx) - __bfloat162float(h0_)); \
    __nv_bfloat16 l1_ = __float2bfloat16_rn((vy) - __bfloat162float(h1_)); \
    hp_ = (unsigned)__bfloat16_as_ushort(h0_) | ((unsigned)__bfloat16_as_ushort(h1_) << 16); \
    lp_ = (unsigned)__bfloat16_as_ushort(l0_) | ((unsigned)__bfloat16_as_ushort(l1_) << 16); }

// CFG 1: out(g_h1) = relu(g_agg@w1^T + b + x(param a2)@w2^T)   [NPASS=2]
// CFG 2: out(param) = g_agg@w1^T + b + g_h1@w2^T               [NPASS=2]
// CFG 3: out(param) = a2(param)@w1^T + b                       [NPASS=1]
template <int CFG>
__global__ void __launch_bounds__(256)
layer_mma(const float* __restrict__ a2p, const float* __restrict__ w1p,
          const float* __restrict__ w2p, const float* __restrict__ bias,
          float* __restrict__ outp, int n) {
    __shared__ __align__(16) char sm[30720];

    const bool RELU = (CFG == 1);
    const int NPASS = (CFG == 3) ? 1 : 2;
    float* out = (CFG == 1) ? (float*)g_h1 : outp;

    int tid = threadIdx.x, lane = tid & 31, wid = tid >> 5;
    int wm = wid & 1, wn = wid >> 1;           // 2 m-warps x 4 n-warps
    int q4 = lane >> 2, r4 = lane & 3;
    int m0 = blockIdx.x * 64;

    DACC(0, 0); DACC(0, 1); DACC(0, 2); DACC(0, 3);
    DACC(1, 0); DACC(1, 1); DACC(1, 2); DACC(1, 3);

    unsigned aBase = (unsigned)((wm * 32 + q4) * 80 + r4 * 4);
    unsigned wBase = (unsigned)(10240 + (wn * 32 + q4) * 80 + r4 * 4);

    for (int p = 0; p < NPASS; p++) {
        const float* ap;
        if (CFG == 3)      ap = a2p;
        else if (p == 0)   ap = (const float*)g_agg;
        else if (CFG == 1) ap = a2p;
        else               ap = (const float*)g_h1;
        const float* wp = (p == 0) ? w1p : w2p;
        const float4* a4 = reinterpret_cast<const float4*>(ap);
        const float4* w4 = reinterpret_cast<const float4*>(wp);

        for (int ck = 0; ck < 4; ck++) {
            __syncthreads();
            // A: 64 rows x 32 k fp32 -> split planes. 2 float4/thread.
#pragma unroll
            for (int i = 0; i < 2; i++) {
                int f = tid * 2 + i;                 // 0..511
                int row = f >> 3, j = f & 7;
                float4 v = make_float4(0.f, 0.f, 0.f, 0.f);
                if (m0 + row < n) v = a4[(size_t)(m0 + row) * 32 + ck * 8 + j];
                unsigned hp0, lp0, hp1, lp1;
                SPLITPACK(v.x, v.y, hp0, lp0);
                SPLITPACK(v.z, v.w, hp1, lp1);
                *reinterpret_cast<uint2*>(sm + row * 80 + j * 8) = make_uint2(hp0, hp1);
                *reinterpret_cast<uint2*>(sm + 5120 + row * 80 + j * 8) = make_uint2(lp0, lp1);
            }
            // W: 128 rows x 32 k fp32 -> split planes. 4 float4/thread.
#pragma unroll
            for (int i = 0; i < 4; i++) {
                int f = tid + i * 256;               // 0..1023
                int row = f >> 3, j = f & 7;
                float4 v = w4[(size_t)row * 32 + ck * 8 + j];
                unsigned hp0, lp0, hp1, lp1;
                SPLITPACK(v.x, v.y, hp0, lp0);
                SPLITPACK(v.z, v.w, hp1, lp1);
                *reinterpret_cast<uint2*>(sm + 10240 + row * 80 + j * 8) = make_uint2(hp0, hp1);
                *reinterpret_cast<uint2*>(sm + 20480 + row * 80 + j * 8) = make_uint2(lp0, lp1);
            }
            __syncthreads();
            DEC_KS(0u)
            DEC_KS(32u)
        }
    }

    DEPI(0, 0) DEPI(0, 1) DEPI(0, 2) DEPI(0, 3)
    DEPI(1, 0) DEPI(1, 1) DEPI(1, 2) DEPI(1, 3)
}

// ---------------- launch ------------------------------------------------------
extern "C" void kernel_launch(void* const* d_in, const int* in_sizes, int n_in,
                              void* d_out, int out_size) {
    const float* x     = (const float*)d_in[0];
    const int*   xedge = (const int*)d_in[1];      // int32 [2, E]
    const float* w1l   = (const float*)d_in[2];
    const float* b1l   = (const float*)d_in[3];
    const float* w1r   = (const float*)d_in[4];
    const float* w2l   = (const float*)d_in[5];
    const float* b2l   = (const float*)d_in[6];
    const float* w2r   = (const float*)d_in[7];
    const float* wdec  = (const float*)d_in[8];
    const float* bdec  = (const float*)d_in[9];

    float* out_h  = (float*)d_out;
    float* out_dx = out_h + (size_t)N_NODES * F;

    const int agg_blocks = (N_NODES + 7) / 8;          // 12500
    const int mma_blocks = (N_NODES + 63) / 64;        // 1563

    // CSR build
    zero_kernel<<<(N_NODES + 255) / 256, 256>>>();
    hist_kernel<<<(N_EDGES + 255) / 256, 256>>>(xedge);
    scan1_kernel<<<NB_SCAN, SCAN_B>>>();
    scan2_kernel<<<1, 256>>>();
    scan3_kernel<<<NB_SCAN, SCAN_B>>>();
    fill_kernel<<<(N_EDGES + 255) / 256, 256>>>(xedge);

    // Layer 1: agg(x) -> g_agg; g_h1 = relu(g_agg@w1l^T + b1l + x@w1r^T)
    agg_kernel<0><<<agg_blocks, 256>>>(x);
    layer_mma<1><<<mma_blocks, 256>>>(x, w1l, w1r, b1l, nullptr, N_NODES);

    // Layer 2: agg(g_h1) -> g_agg; out_h = g_agg@w2l^T + b2l + g_h1@w2r^T
    agg_kernel<1><<<agg_blocks, 256>>>(nullptr);
    layer_mma<2><<<mma_blocks, 256>>>(nullptr, w2l, w2r, b2l, out_h, N_NODES);

    // Decoder: out_dx = out_h@wdec^T + bdec
    layer_mma<3><<<mma_blocks, 256>>>(out_h, wdec, nullptr, bdec, out_dx, N_NODES);
}